// round 14
// baseline (speedup 1.0000x reference)
#include <cuda_runtime.h>

#define BATCH 32
#define LC 512
#define LQ 64
#define DIM 1024

typedef unsigned long long u64;

__device__ __forceinline__ u64 ffma2(u64 a, u64 b, u64 c) {
    u64 d;
    asm("fma.rn.f32x2 %0, %1, %2, %3;" : "=l"(d) : "l"(a), "l"(b), "l"(c));
    return d;
}
__device__ __forceinline__ u64 pack2(float x, float y) {
    u64 d;
    asm("mov.b64 %0, {%1, %2};" : "=l"(d) : "f"(x), "f"(y));
    return d;
}
__device__ __forceinline__ float2 unpack2(u64 v) {
    float2 r;
    asm("mov.b64 {%0, %1}, %2;" : "=f"(r.x), "=f"(r.y) : "l"(v));
    return r;
}
__device__ __forceinline__ float pairsum(u64 v) {
    float2 r = unpack2(v);
    return r.x + r.y;
}
__device__ __forceinline__ void cp16(unsigned saddr, const void* gaddr) {
    asm volatile("cp.async.cg.shared.global [%0], [%1], 16;"
                 :: "r"(saddr), "l"(gaddr) : "memory");
}
#define CP_COMMIT() asm volatile("cp.async.commit_group;" ::: "memory")
#define CP_WAIT0()  asm volatile("cp.async.wait_group 0;" ::: "memory")
#define CP_WAIT1()  asm volatile("cp.async.wait_group 1;" ::: "memory")

// ---------------- scratch -----------------------------------------------------
__device__ float g_s1[BATCH * LQ];          // q @ proj_q
__device__ float g_qs[BATCH * LQ * DIM];    // q * proj_cq (8 MiB)
__device__ float g_sim[BATCH * LC * LQ];    // sim WITHOUT s0 (softmax-invariant)
__device__ float g_m[BATCH * LC];           // rowmax(sim') + s0  (for q2c path)
__device__ float g_q2c[BATCH * DIM];        // query-to-context vector

// ---------------- K0: q-side prep: s1, qs = q*pcq, zero q2c ------------------
__global__ void k_pre_q(const float* __restrict__ q, const float* __restrict__ pq,
                        const float* __restrict__ pcq) {
    int gtid = blockIdx.x * blockDim.x + threadIdx.x;
    if (gtid < BATCH * DIM) g_q2c[gtid] = 0.f;
    int r = gtid >> 5;                  // 0..2047
    int lane = threadIdx.x & 31;
    const float* src = q + (size_t)r * DIM;
    float* dst = g_qs + (size_t)r * DIM;
    float s = 0.f;
#pragma unroll
    for (int i = 0; i < 8; i++) {
        int k = (lane + i * 32) * 4;
        float4 v  = *(const float4*)(src + k);
        float4 pp = *(const float4*)(pq + k);
        s += v.x * pp.x + v.y * pp.y + v.z * pp.z + v.w * pp.w;
        float4 pv = *(const float4*)(pcq + k);
        float4 o = {v.x * pv.x, v.y * pv.y, v.z * pv.z, v.w * pv.w};
        *(float4*)(dst + k) = o;
    }
#pragma unroll
    for (int o = 16; o; o >>= 1) s += __shfl_xor_sync(0xffffffffu, s, o);
    if (lane == 0) g_s1[r] = s;
}

// ---------------- K1: sim' GEMM + per-tile fused s0 ; m = rowmax + s0 -------
#define KT 32
#define AW 36
__global__ void __launch_bounds__(128, 6)
k_sim(const float* __restrict__ c, const float* __restrict__ pc) {
    __shared__ __align__(16) float As[2][32][AW];   // 9 KB
    __shared__ __align__(16) float Bs[2][64][AW];   // 18 KB
    __shared__ __align__(16) float pc_s[2][32];     // 256 B
    __shared__ float s0_s[32];

    int b = blockIdx.y, cm = blockIdx.x;
    int tl = threadIdx.x;
    int tx = tl & 15;          // n-thread
    int ty = tl >> 4;          // m-thread (0..7)

    const float* cA = c + ((size_t)b * LC + cm * 32) * DIM;
    const float* cB = g_qs + (size_t)b * LQ * DIM;

    int lrow = tl >> 3;             // 0..15
    int lkp = (tl & 7) * 4;         // 0..28
    const float* gA0 = cA + (size_t)lrow * DIM + lkp;
    const float* gB0 = cB + (size_t)lrow * DIM + lkp;
    unsigned saA = (unsigned)__cvta_generic_to_shared(&As[0][lrow][lkp]);
    unsigned saB = (unsigned)__cvta_generic_to_shared(&Bs[0][lrow][lkp]);
    unsigned saP = (unsigned)__cvta_generic_to_shared(&pc_s[0][0]);
    const unsigned SA = 32 * AW * 4;
    const unsigned SB = 64 * AW * 4;
    const unsigned R16 = 16 * AW * 4;

    int srow = tl >> 2;
    int sq = (tl & 3) * 8;

    u64 acc[4][4];
#pragma unroll
    for (int i = 0; i < 4; i++)
#pragma unroll
        for (int j = 0; j < 4; j++) acc[i][j] = 0ull;
    u64 s0acc = 0ull;

    cp16(saA, gA0);
    cp16(saA + R16, gA0 + 16 * DIM);
#pragma unroll
    for (int i = 0; i < 4; i++)
        cp16(saB + i * R16, gB0 + (size_t)(16 * i) * DIM);
    if (tl < 8) cp16(saP + tl * 16, pc + tl * 4);
    CP_COMMIT();

    for (int it = 0; it < DIM / KT; it++) {
        int nit = (it + 1 < DIM / KT) ? it + 1 : it;
        unsigned nb = (it + 1) & 1;
        cp16(saA + nb * SA, gA0 + nit * KT);
        cp16(saA + nb * SA + R16, gA0 + 16 * DIM + nit * KT);
#pragma unroll
        for (int i = 0; i < 4; i++)
            cp16(saB + nb * SB + i * R16, gB0 + (size_t)(16 * i) * DIM + nit * KT);
        if (tl < 8) cp16(saP + nb * 128 + tl * 16, pc + nit * KT + tl * 4);
        CP_COMMIT();
        CP_WAIT1();
        __syncthreads();

        int pp = it & 1;
#pragma unroll
        for (int kk4 = 0; kk4 < KT / 4; kk4++) {
            ulonglong2 am[4], bn[4];
#pragma unroll
            for (int i = 0; i < 4; i++)
                am[i] = *(const ulonglong2*)&As[pp][ty + 8 * i][kk4 * 4];
#pragma unroll
            for (int j = 0; j < 4; j++)
                bn[j] = *(const ulonglong2*)&Bs[pp][tx + 16 * j][kk4 * 4];
#pragma unroll
            for (int i = 0; i < 4; i++)
#pragma unroll
                for (int j = 0; j < 4; j++) {
                    acc[i][j] = ffma2(am[i].x, bn[j].x, acc[i][j]);
                    acc[i][j] = ffma2(am[i].y, bn[j].y, acc[i][j]);
                }
        }

        // fused s0 side pass over the resident As tile
        {
            ulonglong2 cv0 = *(const ulonglong2*)&As[pp][srow][sq];
            ulonglong2 cv1 = *(const ulonglong2*)&As[pp][srow][sq + 4];
            ulonglong2 pp0 = *(const ulonglong2*)&pc_s[pp][sq];
            ulonglong2 pp1 = *(const ulonglong2*)&pc_s[pp][sq + 4];
            s0acc = ffma2(cv0.x, pp0.x, s0acc);
            s0acc = ffma2(cv0.y, pp0.y, s0acc);
            s0acc = ffma2(cv1.x, pp1.x, s0acc);
            s0acc = ffma2(cv1.y, pp1.y, s0acc);
        }
        __syncthreads();
    }

    float s0p = pairsum(s0acc);
    s0p += __shfl_xor_sync(0xffffffffu, s0p, 1);
    s0p += __shfl_xor_sync(0xffffffffu, s0p, 2);
    if ((tl & 3) == 0) s0_s[srow] = s0p;
    __syncthreads();

    float (*sim_s)[68] = (float(*)[68])&As[0][0][0];
    float s1v[4];
#pragma unroll
    for (int j = 0; j < 4; j++) s1v[j] = g_s1[b * LQ + tx + 16 * j];
#pragma unroll
    for (int i = 0; i < 4; i++) {
        int m = ty + 8 * i;
        float rm = -3.4e38f;
        float vals[4];
#pragma unroll
        for (int j = 0; j < 4; j++) {
            vals[j] = pairsum(acc[i][j]) + s1v[j];
            rm = fmaxf(rm, vals[j]);
        }
#pragma unroll
        for (int o = 8; o; o >>= 1) rm = fmaxf(rm, __shfl_xor_sync(0xffffffffu, rm, o));
#pragma unroll
        for (int j = 0; j < 4; j++) sim_s[m][tx + 16 * j] = vals[j];
        if (tx == 0) g_m[b * LC + cm * 32 + m] = rm + s0_s[m];
    }
    __syncthreads();

#pragma unroll
    for (int i = 0; i < 4; i++) {
        int idx = tl + 128 * i;
        int wrow = idx >> 4;
        int wcol = (idx & 15) * 4;
        *(float4*)&g_sim[((size_t)b * LC + cm * 32 + wrow) * LQ + wcol] =
            *(const float4*)&sim_s[wrow][wcol];
    }
}

// ---------------- K2: q2c accumulate + write out slice 0 (= c) ---------------
// grid (8, B): 64 c-rows per block, r10 config; slice-0 stores ride on the
// existing c-read (zero extra reads).
__global__ void k_q2c(const float* __restrict__ c, float* __restrict__ out) {
    __shared__ float wm[LC];
    __shared__ float red[256];
    int b = blockIdx.y, cb = blockIdx.x;
    int t = threadIdx.x;
    float v0 = g_m[b * LC + t];
    float v1 = g_m[b * LC + 256 + t];
    red[t] = fmaxf(v0, v1);
    __syncthreads();
#pragma unroll
    for (int s = 128; s > 0; s >>= 1) {
        if (t < s) red[t] = fmaxf(red[t], red[t + s]);
        __syncthreads();
    }
    float mx = red[0];
    __syncthreads();
    float e0 = expf(v0 - mx), e1 = expf(v1 - mx);
    wm[t] = e0;
    wm[t + 256] = e1;
    red[t] = e0 + e1;
    __syncthreads();
#pragma unroll
    for (int s = 128; s > 0; s >>= 1) {
        if (t < s) red[t] += red[t + s];
        __syncthreads();
    }
    float inv = 1.f / red[0];
    __syncthreads();

    float4 acc = {0.f, 0.f, 0.f, 0.f};
    const float* cb0 = c + ((size_t)b * LC + cb * 64) * DIM + (t << 2);
    float* ob0 = out + ((size_t)b * LC + cb * 64) * (4 * DIM) + (t << 2);
#pragma unroll 4
    for (int cr = 0; cr < 64; cr++) {
        float w = wm[cb * 64 + cr] * inv;
        float4 cv = *(const float4*)(cb0 + (size_t)cr * DIM);
        *(float4*)(ob0 + (size_t)cr * 4 * DIM) = cv;   // out slice 0 = c
        acc.x = fmaf(w, cv.x, acc.x);
        acc.y = fmaf(w, cv.y, acc.y);
        acc.z = fmaf(w, cv.z, acc.z);
        acc.w = fmaf(w, cv.w, acc.w);
    }
    float* dst = g_q2c + b * DIM + (t << 2);
    atomicAdd(dst + 0, acc.x);
    atomicAdd(dst + 1, acc.y);
    atomicAdd(dst + 2, acc.z);
    atomicAdd(dst + 3, acc.w);
}

// ---------------- K3: softmax rows, c2q = a @ q, writes slices 1,2,3 ---------
// grid (LC/RT, 4, BATCH) = 1024 blocks; 64 rows x 256 d-cols per block.
#define RT 64
#define DC 128
#define DQ 256
#define QW (DC + 4)
__global__ void __launch_bounds__(256, 2)
k_out(const float* __restrict__ c, const float* __restrict__ q,
      float* __restrict__ out) {
    __shared__ __align__(16) float a_sT[LQ][RT + 2];     // 16.9 KB
    __shared__ __align__(16) float q_s[2][LQ][QW];       // 67.6 KB
    int ct = blockIdx.x, dqi = blockIdx.y, b = blockIdx.z;
    int t = threadIdx.x;
    int warp = t >> 5, lane = t & 31;
    int dq0 = dqi * DQ;

    const float* qb = q + (size_t)b * LQ * DIM;

    // prefetch q chunk 0 while softmax runs
    {
        unsigned sbase = (unsigned)__cvta_generic_to_shared(&q_s[0][0][0]);
#pragma unroll
        for (int i = 0; i < 8; i++) {
            int idx = t + i * 256;
            int qr = idx >> 5;
            int qc = (idx & 31) * 4;
            cp16(sbase + (qr * QW + qc) * 4, qb + (size_t)qr * DIM + dq0 + qc);
        }
        CP_COMMIT();
    }

    // row softmax (g_sim lacks s0; g_m includes it — constant shift cancels)
#pragma unroll
    for (int i = 0; i < 8; i++) {
        int r = warp * 8 + i;
        int row = ct * RT + r;
        size_t sbase = ((size_t)b * LC + row) * LQ;
        float m = g_m[b * LC + row];
        float v0 = expf(g_sim[sbase + lane] - m);
        float v1 = expf(g_sim[sbase + lane + 32] - m);
        float s = v0 + v1;
#pragma unroll
        for (int o = 16; o; o >>= 1) s += __shfl_xor_sync(0xffffffffu, s, o);
        float inv = 1.f / s;
        a_sT[lane][r] = v0 * inv;
        a_sT[lane + 32][r] = v1 * inv;
    }

    int rbase = warp * 8;        // 4 row-pairs per warp

#pragma unroll
    for (int it = 0; it < DQ / DC; it++) {
        int dc = dq0 + it * DC;
        if (it + 1 < DQ / DC) {
            unsigned sbase = (unsigned)__cvta_generic_to_shared(&q_s[it ^ 1][0][0]);
#pragma unroll
            for (int i = 0; i < 8; i++) {
                int idx = t + i * 256;
                int qr = idx >> 5;
                int qc = (idx & 31) * 4;
                cp16(sbase + (qr * QW + qc) * 4,
                     qb + (size_t)qr * DIM + dc + DC + qc);
            }
            CP_COMMIT();
            CP_WAIT1();
        } else {
            CP_WAIT0();
        }
        __syncthreads();

        int d0 = dc + (lane << 2);
        float4 cv[8];
#pragma unroll
        for (int p = 0; p < 4; p++)
#pragma unroll
            for (int e = 0; e < 2; e++) {
                int row = ct * RT + rbase + 2 * p + e;
                cv[2 * p + e] = *(const float4*)(c + ((size_t)b * LC + row) * DIM + d0);
            }

        u64 acc[4][4];
#pragma unroll
        for (int p = 0; p < 4; p++)
#pragma unroll
            for (int d = 0; d < 4; d++) acc[p][d] = 0ull;

#pragma unroll 8
        for (int qq = 0; qq < LQ; qq++) {
            float4 qv = *(const float4*)&q_s[it][qq][lane << 2];
            u64 qd[4] = {pack2(qv.x, qv.x), pack2(qv.y, qv.y),
                         pack2(qv.z, qv.z), pack2(qv.w, qv.w)};
            u64 ar[4];
#pragma unroll
            for (int p = 0; p < 4; p++)
                ar[p] = *(const u64*)&a_sT[qq][rbase + 2 * p];
#pragma unroll
            for (int p = 0; p < 4; p++)
#pragma unroll
                for (int d = 0; d < 4; d++)
                    acc[p][d] = ffma2(ar[p], qd[d], acc[p][d]);
        }

        float4 qc4 = *(const float4*)(g_q2c + b * DIM + d0);
#pragma unroll
        for (int p = 0; p < 4; p++) {
            float2 u0 = unpack2(acc[p][0]);
            float2 u1 = unpack2(acc[p][1]);
            float2 u2 = unpack2(acc[p][2]);
            float2 u3 = unpack2(acc[p][3]);
            float4 arow[2] = {{u0.x, u1.x, u2.x, u3.x}, {u0.y, u1.y, u2.y, u3.y}};
#pragma unroll
            for (int e = 0; e < 2; e++) {
                int row = ct * RT + rbase + 2 * p + e;
                float4 a4 = arow[e];
                float4 cw = cv[2 * p + e];
                float* ob = out + ((size_t)b * LC + row) * (4 * DIM) + d0;
                *(float4*)(ob + DIM) = a4;
                float4 t2 = {cw.x * qc4.x, cw.y * qc4.y, cw.z * qc4.z, cw.w * qc4.w};
                *(float4*)(ob + 2 * DIM) = t2;
                float4 t3 = {cw.x * a4.x, cw.y * a4.y, cw.z * a4.z, cw.w * a4.w};
                *(float4*)(ob + 3 * DIM) = t3;
            }
        }
    }
}

// ---------------- launch -----------------------------------------------------
extern "C" void kernel_launch(void* const* d_in, const int* in_sizes, int n_in,
                              void* d_out, int out_size) {
    const float* c   = (const float*)d_in[0];
    const float* q   = (const float*)d_in[1];
    const float* pc  = (const float*)d_in[2];
    const float* pq  = (const float*)d_in[3];
    const float* pcq = (const float*)d_in[4];
    float* out = (float*)d_out;
    (void)in_sizes; (void)n_in; (void)out_size;

    k_pre_q<<<BATCH * LQ * 32 / 256, 256>>>(q, pq, pcq);
    k_sim<<<dim3(LC / 32, BATCH), 128>>>(c, pc);
    k_q2c<<<dim3(8, BATCH), 256>>>(c, out);
    k_out<<<dim3(LC / RT, DIM / DQ, BATCH), 256>>>(c, q, out);
}

// round 15
// speedup vs baseline: 1.0280x; 1.0280x over previous
#include <cuda_runtime.h>

#define BATCH 32
#define LC 512
#define LQ 64
#define DIM 1024

typedef unsigned long long u64;

__device__ __forceinline__ u64 ffma2(u64 a, u64 b, u64 c) {
    u64 d;
    asm("fma.rn.f32x2 %0, %1, %2, %3;" : "=l"(d) : "l"(a), "l"(b), "l"(c));
    return d;
}
__device__ __forceinline__ u64 pack2(float x, float y) {
    u64 d;
    asm("mov.b64 %0, {%1, %2};" : "=l"(d) : "f"(x), "f"(y));
    return d;
}
__device__ __forceinline__ float2 unpack2(u64 v) {
    float2 r;
    asm("mov.b64 {%0, %1}, %2;" : "=f"(r.x), "=f"(r.y) : "l"(v));
    return r;
}
__device__ __forceinline__ float pairsum(u64 v) {
    float2 r = unpack2(v);
    return r.x + r.y;
}
__device__ __forceinline__ void cp16(unsigned saddr, const void* gaddr) {
    asm volatile("cp.async.cg.shared.global [%0], [%1], 16;"
                 :: "r"(saddr), "l"(gaddr) : "memory");
}
#define CP_COMMIT() asm volatile("cp.async.commit_group;" ::: "memory")
#define CP_WAIT0()  asm volatile("cp.async.wait_group 0;" ::: "memory")
#define CP_WAIT1()  asm volatile("cp.async.wait_group 1;" ::: "memory")

// ---------------- scratch -----------------------------------------------------
__device__ float g_s1[BATCH * LQ];          // q @ proj_q
__device__ float g_qs[BATCH * LQ * DIM];    // q * proj_cq (8 MiB)
__device__ float g_sim[BATCH * LC * LQ];    // sim WITHOUT s0 (softmax-invariant)
__device__ float g_m[BATCH * LC];           // rowmax(sim') + s0  (for q2c path)
__device__ float g_q2c[BATCH * DIM];        // query-to-context vector

// ---------------- K0: q-side prep: s1, qs = q*pcq, zero q2c ------------------
__global__ void k_pre_q(const float* __restrict__ q, const float* __restrict__ pq,
                        const float* __restrict__ pcq) {
    int gtid = blockIdx.x * blockDim.x + threadIdx.x;
    if (gtid < BATCH * DIM) g_q2c[gtid] = 0.f;
    int r = gtid >> 5;                  // 0..2047
    int lane = threadIdx.x & 31;
    const float* src = q + (size_t)r * DIM;
    float* dst = g_qs + (size_t)r * DIM;
    float s = 0.f;
#pragma unroll
    for (int i = 0; i < 8; i++) {
        int k = (lane + i * 32) * 4;
        float4 v  = *(const float4*)(src + k);
        float4 pp = *(const float4*)(pq + k);
        s += v.x * pp.x + v.y * pp.y + v.z * pp.z + v.w * pp.w;
        float4 pv = *(const float4*)(pcq + k);
        float4 o = {v.x * pv.x, v.y * pv.y, v.z * pv.z, v.w * pv.w};
        *(float4*)(dst + k) = o;
    }
#pragma unroll
    for (int o = 16; o; o >>= 1) s += __shfl_xor_sync(0xffffffffu, s, o);
    if (lane == 0) g_s1[r] = s;
}

// ---------------- K1: sim' GEMM + fused s0 + slice-0 writeback ---------------
// tile 32(m)x64(n), 128 threads, micro 4x4 f32x2, cp.async double buffer.
// Per tile: s0 side pass + copy resident c-tile (As) to out[...,0:D]
// (writes ride on k_sim's idle DRAM pipe; deletes the stores elsewhere).
#define KT 32
#define AW 36
__global__ void __launch_bounds__(128, 6)
k_sim(const float* __restrict__ c, const float* __restrict__ pc,
      float* __restrict__ out) {
    __shared__ __align__(16) float As[2][32][AW];   // 9 KB
    __shared__ __align__(16) float Bs[2][64][AW];   // 18 KB
    __shared__ __align__(16) float pc_s[2][32];     // 256 B
    __shared__ float s0_s[32];

    int b = blockIdx.y, cm = blockIdx.x;
    int tl = threadIdx.x;
    int tx = tl & 15;          // n-thread
    int ty = tl >> 4;          // m-thread (0..7)

    const float* cA = c + ((size_t)b * LC + cm * 32) * DIM;
    const float* cB = g_qs + (size_t)b * LQ * DIM;

    int lrow = tl >> 3;             // 0..15
    int lkp = (tl & 7) * 4;         // 0..28
    const float* gA0 = cA + (size_t)lrow * DIM + lkp;
    const float* gB0 = cB + (size_t)lrow * DIM + lkp;
    unsigned saA = (unsigned)__cvta_generic_to_shared(&As[0][lrow][lkp]);
    unsigned saB = (unsigned)__cvta_generic_to_shared(&Bs[0][lrow][lkp]);
    unsigned saP = (unsigned)__cvta_generic_to_shared(&pc_s[0][0]);
    const unsigned SA = 32 * AW * 4;
    const unsigned SB = 64 * AW * 4;
    const unsigned R16 = 16 * AW * 4;

    int srow = tl >> 2;
    int sq = (tl & 3) * 8;

    // slice-0 writeback ownership: rows wr0, wr0+... : idx = tl + 128*i
    // row = idx>>3 (0..31), k-quad = (idx&7)*4
    float* outb = out + ((size_t)b * LC + cm * 32) * (4 * DIM);

    u64 acc[4][4];
#pragma unroll
    for (int i = 0; i < 4; i++)
#pragma unroll
        for (int j = 0; j < 4; j++) acc[i][j] = 0ull;
    u64 s0acc = 0ull;

    cp16(saA, gA0);
    cp16(saA + R16, gA0 + 16 * DIM);
#pragma unroll
    for (int i = 0; i < 4; i++)
        cp16(saB + i * R16, gB0 + (size_t)(16 * i) * DIM);
    if (tl < 8) cp16(saP + tl * 16, pc + tl * 4);
    CP_COMMIT();

    for (int it = 0; it < DIM / KT; it++) {
        int nit = (it + 1 < DIM / KT) ? it + 1 : it;
        unsigned nb = (it + 1) & 1;
        cp16(saA + nb * SA, gA0 + nit * KT);
        cp16(saA + nb * SA + R16, gA0 + 16 * DIM + nit * KT);
#pragma unroll
        for (int i = 0; i < 4; i++)
            cp16(saB + nb * SB + i * R16, gB0 + (size_t)(16 * i) * DIM + nit * KT);
        if (tl < 8) cp16(saP + nb * 128 + tl * 16, pc + nit * KT + tl * 4);
        CP_COMMIT();
        CP_WAIT1();
        __syncthreads();

        int pp = it & 1;
#pragma unroll
        for (int kk4 = 0; kk4 < KT / 4; kk4++) {
            ulonglong2 am[4], bn[4];
#pragma unroll
            for (int i = 0; i < 4; i++)
                am[i] = *(const ulonglong2*)&As[pp][ty + 8 * i][kk4 * 4];
#pragma unroll
            for (int j = 0; j < 4; j++)
                bn[j] = *(const ulonglong2*)&Bs[pp][tx + 16 * j][kk4 * 4];
#pragma unroll
            for (int i = 0; i < 4; i++)
#pragma unroll
                for (int j = 0; j < 4; j++) {
                    acc[i][j] = ffma2(am[i].x, bn[j].x, acc[i][j]);
                    acc[i][j] = ffma2(am[i].y, bn[j].y, acc[i][j]);
                }
        }

        // fused s0 side pass over the resident As tile
        {
            ulonglong2 cv0 = *(const ulonglong2*)&As[pp][srow][sq];
            ulonglong2 cv1 = *(const ulonglong2*)&As[pp][srow][sq + 4];
            ulonglong2 pp0 = *(const ulonglong2*)&pc_s[pp][sq];
            ulonglong2 pp1 = *(const ulonglong2*)&pc_s[pp][sq + 4];
            s0acc = ffma2(cv0.x, pp0.x, s0acc);
            s0acc = ffma2(cv0.y, pp0.y, s0acc);
            s0acc = ffma2(cv1.x, pp1.x, s0acc);
            s0acc = ffma2(cv1.y, pp1.y, s0acc);
        }

        // slice-0 writeback from the resident c-tile (2 LDS.128 + 2 STG.128)
#pragma unroll
        for (int i = 0; i < 2; i++) {
            int idx = tl + 128 * i;
            int wrow = idx >> 3;            // 0..31
            int wk = (idx & 7) * 4;         // 0..28
            float4 v = *(const float4*)&As[pp][wrow][wk];
            *(float4*)(outb + (size_t)wrow * (4 * DIM) + it * KT + wk) = v;
        }
        __syncthreads();
    }

    float s0p = pairsum(s0acc);
    s0p += __shfl_xor_sync(0xffffffffu, s0p, 1);
    s0p += __shfl_xor_sync(0xffffffffu, s0p, 2);
    if ((tl & 3) == 0) s0_s[srow] = s0p;
    __syncthreads();

    float (*sim_s)[68] = (float(*)[68])&As[0][0][0];
    float s1v[4];
#pragma unroll
    for (int j = 0; j < 4; j++) s1v[j] = g_s1[b * LQ + tx + 16 * j];
#pragma unroll
    for (int i = 0; i < 4; i++) {
        int m = ty + 8 * i;
        float rm = -3.4e38f;
        float vals[4];
#pragma unroll
        for (int j = 0; j < 4; j++) {
            vals[j] = pairsum(acc[i][j]) + s1v[j];
            rm = fmaxf(rm, vals[j]);
        }
#pragma unroll
        for (int o = 8; o; o >>= 1) rm = fmaxf(rm, __shfl_xor_sync(0xffffffffu, rm, o));
#pragma unroll
        for (int j = 0; j < 4; j++) sim_s[m][tx + 16 * j] = vals[j];
        if (tx == 0) g_m[b * LC + cm * 32 + m] = rm + s0_s[m];
    }
    __syncthreads();

#pragma unroll
    for (int i = 0; i < 4; i++) {
        int idx = tl + 128 * i;
        int wrow = idx >> 4;
        int wcol = (idx & 15) * 4;
        *(float4*)&g_sim[((size_t)b * LC + cm * 32 + wrow) * LQ + wcol] =
            *(const float4*)&sim_s[wrow][wcol];
    }
}

// ---------------- K2: q2c[b,:] = softmax_c(m) @ c[b] ------------------------
// grid (8, B): 64 c-rows per block — pure r10 config (17.7us measured)
__global__ void k_q2c(const float* __restrict__ c) {
    __shared__ float wm[LC];
    __shared__ float red[256];
    int b = blockIdx.y, cb = blockIdx.x;
    int t = threadIdx.x;
    float v0 = g_m[b * LC + t];
    float v1 = g_m[b * LC + 256 + t];
    red[t] = fmaxf(v0, v1);
    __syncthreads();
#pragma unroll
    for (int s = 128; s > 0; s >>= 1) {
        if (t < s) red[t] = fmaxf(red[t], red[t + s]);
        __syncthreads();
    }
    float mx = red[0];
    __syncthreads();
    float e0 = expf(v0 - mx), e1 = expf(v1 - mx);
    wm[t] = e0;
    wm[t + 256] = e1;
    red[t] = e0 + e1;
    __syncthreads();
#pragma unroll
    for (int s = 128; s > 0; s >>= 1) {
        if (t < s) red[t] += red[t + s];
        __syncthreads();
    }
    float inv = 1.f / red[0];
    __syncthreads();

    float4 acc = {0.f, 0.f, 0.f, 0.f};
    const float* cb0 = c + ((size_t)b * LC + cb * 64) * DIM + (t << 2);
#pragma unroll 4
    for (int cr = 0; cr < 64; cr++) {
        float w = wm[cb * 64 + cr] * inv;
        float4 cv = *(const float4*)(cb0 + (size_t)cr * DIM);
        acc.x = fmaf(w, cv.x, acc.x);
        acc.y = fmaf(w, cv.y, acc.y);
        acc.z = fmaf(w, cv.z, acc.z);
        acc.w = fmaf(w, cv.w, acc.w);
    }
    float* dst = g_q2c + b * DIM + (t << 2);
    atomicAdd(dst + 0, acc.x);
    atomicAdd(dst + 1, acc.y);
    atomicAdd(dst + 2, acc.z);
    atomicAdd(dst + 3, acc.w);
}

// ---------------- K3: softmax rows, c2q = a @ q, writes slices 1,2,3 ---------
// grid (LC/RT, 4, BATCH) = 1024 blocks; 64 rows x 256 d-cols per block.
#define RT 64
#define DC 128
#define DQ 256
#define QW (DC + 4)
__global__ void __launch_bounds__(256, 2)
k_out(const float* __restrict__ c, const float* __restrict__ q,
      float* __restrict__ out) {
    __shared__ __align__(16) float a_sT[LQ][RT + 2];     // 16.9 KB
    __shared__ __align__(16) float q_s[2][LQ][QW];       // 67.6 KB
    int ct = blockIdx.x, dqi = blockIdx.y, b = blockIdx.z;
    int t = threadIdx.x;
    int warp = t >> 5, lane = t & 31;
    int dq0 = dqi * DQ;

    const float* qb = q + (size_t)b * LQ * DIM;

    // prefetch q chunk 0 while softmax runs
    {
        unsigned sbase = (unsigned)__cvta_generic_to_shared(&q_s[0][0][0]);
#pragma unroll
        for (int i = 0; i < 8; i++) {
            int idx = t + i * 256;
            int qr = idx >> 5;
            int qc = (idx & 31) * 4;
            cp16(sbase + (qr * QW + qc) * 4, qb + (size_t)qr * DIM + dq0 + qc);
        }
        CP_COMMIT();
    }

    // row softmax (g_sim lacks s0; g_m includes it — constant shift cancels)
#pragma unroll
    for (int i = 0; i < 8; i++) {
        int r = warp * 8 + i;
        int row = ct * RT + r;
        size_t sbase = ((size_t)b * LC + row) * LQ;
        float m = g_m[b * LC + row];
        float v0 = expf(g_sim[sbase + lane] - m);
        float v1 = expf(g_sim[sbase + lane + 32] - m);
        float s = v0 + v1;
#pragma unroll
        for (int o = 16; o; o >>= 1) s += __shfl_xor_sync(0xffffffffu, s, o);
        float inv = 1.f / s;
        a_sT[lane][r] = v0 * inv;
        a_sT[lane + 32][r] = v1 * inv;
    }

    int rbase = warp * 8;        // 4 row-pairs per warp

#pragma unroll
    for (int it = 0; it < DQ / DC; it++) {
        int dc = dq0 + it * DC;
        if (it + 1 < DQ / DC) {
            unsigned sbase = (unsigned)__cvta_generic_to_shared(&q_s[it ^ 1][0][0]);
#pragma unroll
            for (int i = 0; i < 8; i++) {
                int idx = t + i * 256;
                int qr = idx >> 5;
                int qc = (idx & 31) * 4;
                cp16(sbase + (qr * QW + qc) * 4,
                     qb + (size_t)qr * DIM + dc + DC + qc);
            }
            CP_COMMIT();
            CP_WAIT1();
        } else {
            CP_WAIT0();
        }
        __syncthreads();

        int d0 = dc + (lane << 2);
        float4 cv[8];
#pragma unroll
        for (int p = 0; p < 4; p++)
#pragma unroll
            for (int e = 0; e < 2; e++) {
                int row = ct * RT + rbase + 2 * p + e;
                cv[2 * p + e] = *(const float4*)(c + ((size_t)b * LC + row) * DIM + d0);
            }

        u64 acc[4][4];
#pragma unroll
        for (int p = 0; p < 4; p++)
#pragma unroll
            for (int d = 0; d < 4; d++) acc[p][d] = 0ull;

#pragma unroll 8
        for (int qq = 0; qq < LQ; qq++) {
            float4 qv = *(const float4*)&q_s[it][qq][lane << 2];
            u64 qd[4] = {pack2(qv.x, qv.x), pack2(qv.y, qv.y),
                         pack2(qv.z, qv.z), pack2(qv.w, qv.w)};
            u64 ar[4];
#pragma unroll
            for (int p = 0; p < 4; p++)
                ar[p] = *(const u64*)&a_sT[qq][rbase + 2 * p];
#pragma unroll
            for (int p = 0; p < 4; p++)
#pragma unroll
                for (int d = 0; d < 4; d++)
                    acc[p][d] = ffma2(ar[p], qd[d], acc[p][d]);
        }

        float4 qc4 = *(const float4*)(g_q2c + b * DIM + d0);
#pragma unroll
        for (int p = 0; p < 4; p++) {
            float2 u0 = unpack2(acc[p][0]);
            float2 u1 = unpack2(acc[p][1]);
            float2 u2 = unpack2(acc[p][2]);
            float2 u3 = unpack2(acc[p][3]);
            float4 arow[2] = {{u0.x, u1.x, u2.x, u3.x}, {u0.y, u1.y, u2.y, u3.y}};
#pragma unroll
            for (int e = 0; e < 2; e++) {
                int row = ct * RT + rbase + 2 * p + e;
                float4 a4 = arow[e];
                float4 cw = cv[2 * p + e];
                float* ob = out + ((size_t)b * LC + row) * (4 * DIM) + d0;
                *(float4*)(ob + DIM) = a4;
                float4 t2 = {cw.x * qc4.x, cw.y * qc4.y, cw.z * qc4.z, cw.w * qc4.w};
                *(float4*)(ob + 2 * DIM) = t2;
                float4 t3 = {cw.x * a4.x, cw.y * a4.y, cw.z * a4.z, cw.w * a4.w};
                *(float4*)(ob + 3 * DIM) = t3;
            }
        }
    }
}

// ---------------- launch -----------------------------------------------------
extern "C" void kernel_launch(void* const* d_in, const int* in_sizes, int n_in,
                              void* d_out, int out_size) {
    const float* c   = (const float*)d_in[0];
    const float* q   = (const float*)d_in[1];
    const float* pc  = (const float*)d_in[2];
    const float* pq  = (const float*)d_in[3];
    const float* pcq = (const float*)d_in[4];
    float* out = (float*)d_out;
    (void)in_sizes; (void)n_in; (void)out_size;

    k_pre_q<<<BATCH * LQ * 32 / 256, 256>>>(q, pq, pcq);
    k_sim<<<dim3(LC / 32, BATCH), 128>>>(c, pc, out);
    k_q2c<<<dim3(8, BATCH), 256>>>(c);
    k_out<<<dim3(LC / RT, DIM / DQ, BATCH), 256>>>(c, q, out);
}